// round 16
// baseline (speedup 1.0000x reference)
#include <cuda_runtime.h>
#include <cuda_fp16.h>
#include <math.h>

#define A_N 8192
#define K_N 64
#define D_N 128
#define B_N 16384
#define CVT_BLOCKS 256               // 64 rows per block (8 rows per warp)
#define P_N (A_N + CVT_BLOCKS)       // compact prescaled partials

// fp16 shadow of the embedding table: 16384 rows x 128 halves = 4.19 MB.
// Row r occupies g_Eh[r*32 .. r*32+31], lane l holds halves [4l..4l+3].
__device__ uint2 g_Eh[B_N * 32];
// Prescaled partials: [0,A_N) anchor losses * (1/A_N); [A_N,P_N) block norm sums * (0.25/B_N).
__device__ float g_part[P_N];

__device__ __forceinline__ unsigned int h2_as_u32(__half2 h) {
    return *reinterpret_cast<unsigned int*>(&h);
}
__device__ __forceinline__ __half2 u32_as_h2(unsigned int u) {
    return *reinterpret_cast<__half2*>(&u);
}

__device__ __forceinline__ int load_idx(const void* p, long long i, int is64) {
    return is64 ? (int)((const long long*)p)[i] : ((const int*)p)[i];
}

// Merge two multi-value partial registers at lane-distance s (1 shuffle + selects):
// lanes with (lane&s)==0 end holding x reduced over {l,l^s}; others y reduced.
__device__ __forceinline__ float merge2(float x, float y, int s, int lane) {
    float send = (lane & s) ? x : y;
    float keep = (lane & s) ? y : x;
    float t = __shfl_xor_sync(0xffffffffu, send, s);
    return keep + t;
}

// ---------------------------------------------------------------------------
// Convert E -> fp16 table + per-row L2 norms. 256 blocks x 256 threads; each
// warp handles 8 rows with all 8 float4 loads front-batched (MLP=8 to cover
// the 577-cyc DRAM latency). The 8 norms reduce in ONE pass: merge tree at
// distances 4/8/16 (lane l ends holding row (l>>2)&7's partial) + butterflies
// 2/1. 64 rows/block -> 1 prescaled partial.
// ---------------------------------------------------------------------------
__global__ __launch_bounds__(256) void convert_kernel(const float* __restrict__ E) {
    __shared__ float sN[64];
    const int w = threadIdx.x >> 5;      // warp 0..7
    const int l = threadIdx.x & 31;
    const int base = blockIdx.x * 64 + w * 8;

    // Front-batched independent loads (8 x LDG.128 in flight)
    float4 v[8];
    #pragma unroll
    for (int i = 0; i < 8; i++)
        v[i] = ((const float4*)(E + (long long)(base + i) * D_N))[l];

    // Convert + store fp16 rows
    #pragma unroll
    for (int i = 0; i < 8; i++) {
        uint2 u;
        u.x = h2_as_u32(__floats2half2_rn(v[i].x, v[i].y));
        u.y = h2_as_u32(__floats2half2_rn(v[i].z, v[i].w));
        g_Eh[(base + i) * 32 + l] = u;
    }

    // Per-row squared-norm partials
    float n[8];
    #pragma unroll
    for (int i = 0; i < 8; i++)
        n[i] = v[i].x * v[i].x + v[i].y * v[i].y + v[i].z * v[i].z + v[i].w * v[i].w;

    // Merge tree: after this, lane l holds the FULL sum of row (l>>2)&7
    // (bit2 -> row bit0, bit3 -> row bit1, bit4 -> row bit2), duplicated x4.
    float e[4], f[2], g;
    #pragma unroll
    for (int m = 0; m < 4; m++) e[m] = merge2(n[2 * m], n[2 * m + 1], 4, l);
    #pragma unroll
    for (int m = 0; m < 2; m++) f[m] = merge2(e[2 * m], e[2 * m + 1], 8, l);
    g = merge2(f[0], f[1], 16, l);
    g += __shfl_xor_sync(0xffffffffu, g, 2);
    g += __shfl_xor_sync(0xffffffffu, g, 1);

    if ((l & 3) == 0) sN[w * 8 + ((l >> 2) & 7)] = sqrtf(g);
    __syncthreads();
    if (threadIdx.x == 0) {
        float t = 0.0f;
        #pragma unroll
        for (int i = 0; i < 64; i++) t += sN[i];
        g_part[A_N + blockIdx.x] = t * (0.25f / (float)B_N);
    }
}

// ---------------------------------------------------------------------------
// N-pair kernel: one block (4 warps) per anchor. ALL row reads from the fp16
// table. NOTE: with lane l holding elements [4l..4l+3], EACH WARP computes the
// FULL a.p by itself after its butterfly (no cross-warp sum!).
// ---------------------------------------------------------------------------
__global__ __launch_bounds__(128) void npair_kernel(
    const void* __restrict__ anc,
    const void* __restrict__ pos,
    const void* __restrict__ neg)
{
    __shared__ float sM[4], sS[4];

    const int t = threadIdx.x;
    const int w = t >> 5;
    const int l = t & 31;
    const int a = blockIdx.x;

    // ---- per-warp dtype detection (1 LDG + 5 shuffles) ----
    unsigned int det = ((const unsigned int*)neg)[a * 64 + 2 * l + 1];
    #pragma unroll
    for (int o = 16; o; o >>= 1) det |= __shfl_xor_sync(0xffffffffu, det, o);
    const int is64 = (det == 0u) ? 1 : 0;

    const int ai = load_idx(anc, a, is64);
    const int pi = load_idx(pos, a, is64);

    // ---- anchor + positive rows from fp16 table ----
    const uint2 au = g_Eh[ai * 32 + l];
    const uint2 pu = g_Eh[pi * 32 + l];
    const float2 a01 = __half22float2(u32_as_h2(au.x));
    const float2 a23 = __half22float2(u32_as_h2(au.y));
    const float2 p01 = __half22float2(u32_as_h2(pu.x));
    const float2 p23 = __half22float2(u32_as_h2(pu.y));

    // ---- a.p: warp-local butterfly gives the FULL dot in every lane ----
    float apf = a01.x * p01.x + a01.y * p01.y + a23.x * p23.x + a23.y * p23.y;
    #pragma unroll
    for (int o = 16; o; o >>= 1) apf += __shfl_xor_sync(0xffffffffu, apf, o);

    // ---- 16 negatives per warp; fp16 gathers (256B/warp-load) ----
    const long long kbase = (long long)a * K_N + (long long)w * 16;
    float d[16];
    #pragma unroll
    for (int j = 0; j < 16; j++) {
        const int nidx = load_idx(neg, kbase + j, is64);
        const uint2 nu = __ldg(&g_Eh[nidx * 32 + l]);
        const float2 n01 = __half22float2(u32_as_h2(nu.x));
        const float2 n23 = __half22float2(u32_as_h2(nu.y));
        d[j] = a01.x * n01.x + a01.y * n01.y + a23.x * n23.x + a23.y * n23.y;
    }

    // ---- merge-tree reduce: 16 dots x 32 lanes in 16 shuffles ----
    float e[8], f[4], g[2], h;
    #pragma unroll
    for (int m = 0; m < 8; m++) e[m] = merge2(d[2 * m], d[2 * m + 1], 16, l);
    #pragma unroll
    for (int m = 0; m < 4; m++) f[m] = merge2(e[2 * m], e[2 * m + 1], 8, l);
    #pragma unroll
    for (int m = 0; m < 2; m++) g[m] = merge2(f[2 * m], f[2 * m + 1], 4, l);
    h = merge2(g[0], g[1], 2, l);
    h += __shfl_xor_sync(0xffffffffu, h, 1);
    const float inner = h - apf;  // lane l holds dot k(l), duplicated x2

    // ---- in-warp logsumexp over this warp's 16 dots ----
    float m1 = inner;
    #pragma unroll
    for (int o = 16; o; o >>= 1) m1 = fmaxf(m1, __shfl_xor_sync(0xffffffffu, m1, o));
    float s1 = __expf(inner - m1);
    #pragma unroll
    for (int o = 16; o; o >>= 1) s1 += __shfl_xor_sync(0xffffffffu, s1, o);
    if (l == 0) { sM[w] = m1; sS[w] = 0.5f * s1; }  // halve: duplicates
    __syncthreads();

    if (t == 0) {
        float M = fmaxf(fmaxf(sM[0], sM[1]), fmaxf(sM[2], sM[3]));
        float S = sS[0] * __expf(sM[0] - M) + sS[1] * __expf(sM[1] - M)
                + sS[2] * __expf(sM[2] - M) + sS[3] * __expf(sM[3] - M);
        const float lse = M + logf(S);
        const float pa = fmaxf(lse, 0.0f) + log1pf(expf(-fabsf(lse)));
        g_part[a] = pa * (1.0f / (float)A_N);
    }
}

// ---------------------------------------------------------------------------
// Deterministic final reduction: all partials prescaled -> uniform sum.
// 8448 floats, single block, fixed order.
// ---------------------------------------------------------------------------
__global__ void final_kernel(float* __restrict__ out) {
    __shared__ float s[32];
    const float4* __restrict__ p4 = (const float4*)g_part;
    float acc = 0.0f;
    for (int i = threadIdx.x; i < P_N / 4; i += 1024) {
        const float4 v = p4[i];
        acc += (v.x + v.y) + (v.z + v.w);
    }
    #pragma unroll
    for (int o = 16; o; o >>= 1) acc += __shfl_xor_sync(0xffffffffu, acc, o);
    const int w = threadIdx.x >> 5, l = threadIdx.x & 31;
    if (l == 0) s[w] = acc;
    __syncthreads();
    if (threadIdx.x == 0) {
        float r = 0.0f;
        for (int i = 0; i < 32; i++) r += s[i];
        out[0] = r;
    }
}

extern "C" void kernel_launch(void* const* d_in, const int* in_sizes, int n_in,
                              void* d_out, int out_size) {
    const float* E   = (const float*)d_in[0];   // image_embed [B, D] f32
    const void*  anc = d_in[1];                 // anc_ind [A]
    const void*  pos = d_in[2];                 // pos_ind [A]
    const void*  neg = d_in[3];                 // neg_ind [A, K]
    float* out = (float*)d_out;

    convert_kernel<<<CVT_BLOCKS, 256>>>(E);
    npair_kernel<<<A_N, 128>>>(anc, pos, neg);
    final_kernel<<<1, 1024>>>(out);
}